// round 14
// baseline (speedup 1.0000x reference)
#include <cuda_runtime.h>
#include <cuda_bf16.h>

#define B_ 64
#define T_ 1024
#define I_ 8
#define H_ 512
#define O_ 2
#define NOISE_STD_ 0.05f
#define ALPHA_ 0.2f

#define NT_    192          // 6 warps: w3=consumer, w2=epilogue, w0/w1/w4/w5=producers
#define RING_  8            // e-ring and h-ring slots (16 KB each)

#define SA_      8192.0f    // 2^13 scale for recurrence dots
#define SO_      2097152.0f // 2^21 scale for output dots
#define MAGIC_F  12582912.0f        // 2^23 + 2^22 round-to-int bias
// Single-warp REDUX of 32 biased floats: bias = 32*0x4B400000 mod 2^32 = 0x68000000.
// Re-bias: + (0x4B400000 - 0x68000000) = 0xE3400000.
#define REBIAS_I ((int)0xE3400000u)

__device__ __forceinline__ float tanh_mufu(float x) {
    float r; asm("tanh.approx.f32 %0, %1;" : "=f"(r) : "f"(x)); return r;
}
__device__ __forceinline__ int redux_add_s32(int v) {
    int r; asm volatile("redux.sync.add.s32 %0, %1, 0xffffffff;" : "=r"(r) : "r"(v)); return r;
}
__device__ __forceinline__ float4 ldsv4(const float* p) {
    float4 v;
    unsigned a = (unsigned)__cvta_generic_to_shared(p);
    asm volatile("ld.volatile.shared.v4.f32 {%0,%1,%2,%3}, [%4];"
                 : "=f"(v.x), "=f"(v.y), "=f"(v.z), "=f"(v.w) : "r"(a));
    return v;
}

__global__ __launch_bounds__(NT_, 1)
void lowrank_rnn_kernel(const float* __restrict__ input,   // (B,T,I)
                        const float* __restrict__ noise,   // (B,T,H)
                        const float* __restrict__ wi,      // (I,H)
                        const float* __restrict__ si,      // (I,)
                        const float* __restrict__ m,       // (H,R)
                        const float* __restrict__ n,       // (H,R)
                        const float* __restrict__ wo,      // (H,O)
                        const float* __restrict__ so,      // (O,)
                        const float* __restrict__ h0,      // (H,)
                        float* __restrict__ out,           // (B,T,O)
                        float* __restrict__ traj)          // (B,T,H)
{
    __shared__ float s_e[RING_][H_];       // e(t) = 0.05nz + alpha*proj + negmc
    __shared__ float s_h[RING_][H_];       // h(t+1) handoff consumer -> epilogue
    __shared__ volatile int s_pcnt[4];     // producers: e ready through step pcnt-1
    __shared__ volatile int s_ccnt;        // consumer: steps finished (h published)
    __shared__ volatile int s_ecnt;        // epilogue: steps consumed

    const int b    = blockIdx.x;
    const int tid  = threadIdx.x;
    const int w    = tid >> 5;
    const int lane = tid & 31;

    const float cm = (ALPHA_ / (float)H_) / SA_;   // alpha/H and 1/Sa folded into m

    if (w != 3 && w != 2) {
        // =================== PRODUCER (warps 0,1,4,5) ===================
        const int pw = (w < 2) ? w : w - 2;        // 0..3
        const int k0 = (pw * 32 + lane) * 4;

        float wif[I_][4];                          // wi * si * alpha
        #pragma unroll
        for (int i = 0; i < I_; ++i) {
            const float4 ww = *(const float4*)(wi + i * H_ + k0);
            const float  s  = si[i] * ALPHA_;
            wif[i][0] = ww.x * s; wif[i][1] = ww.y * s;
            wif[i][2] = ww.z * s; wif[i][3] = ww.w * s;
        }
        float negmc[4];                            // -MAGIC*(m0f+m1f), folded into e
        {
            const float4 mA = *(const float4*)(m + k0 * 2);
            const float4 mB = *(const float4*)(m + k0 * 2 + 4);
            negmc[0] = -MAGIC_F * (mA.x * cm + mA.y * cm);
            negmc[1] = -MAGIC_F * (mA.z * cm + mA.w * cm);
            negmc[2] = -MAGIC_F * (mB.x * cm + mB.y * cm);
            negmc[3] = -MAGIC_F * (mB.z * cm + mB.w * cm);
        }
        const float* nz_base = noise + (size_t)b * T_ * H_ + k0;
        const float* in_base = input + (size_t)b * T_ * I_;

        if (tid == 0) { s_ccnt = 0; s_ecnt = 0; }
        // prologue: produce steps 0..3
        for (int s = 0; s < 4; ++s) {
            const float4 nz = *(const float4*)(nz_base + (size_t)s * H_);
            const float4 x0 = __ldg((const float4*)(in_base + s * I_));
            const float4 x1 = __ldg((const float4*)(in_base + s * I_ + 4));
            const float nza[4] = {nz.x, nz.y, nz.z, nz.w};
            float e[4];
            #pragma unroll
            for (int u = 0; u < 4; ++u) {
                float pp = fmaf(NOISE_STD_, nza[u], negmc[u]);
                pp = fmaf(x0.x, wif[0][u], pp);
                pp = fmaf(x0.y, wif[1][u], pp);
                pp = fmaf(x0.z, wif[2][u], pp);
                pp = fmaf(x0.w, wif[3][u], pp);
                pp = fmaf(x1.x, wif[4][u], pp);
                pp = fmaf(x1.y, wif[5][u], pp);
                pp = fmaf(x1.z, wif[6][u], pp);
                pp = fmaf(x1.w, wif[7][u], pp);
                e[u] = pp;
            }
            *(float4*)&s_e[s][k0] = make_float4(e[0], e[1], e[2], e[3]);
        }
        if (lane == 0) s_pcnt[pw] = 4;
        // preload LDG ring for steps 4..7
        float4 rnz[4], rx0[4], rx1[4];
        #pragma unroll
        for (int j = 0; j < 4; ++j) {
            const int t = 4 + j;
            rnz[j] = *(const float4*)(nz_base + (size_t)t * H_);
            rx0[j] = __ldg((const float4*)(in_base + t * I_));
            rx1[j] = __ldg((const float4*)(in_base + t * I_ + 4));
        }
        __syncthreads();

        int ccached = 0;
        #pragma unroll 4
        for (int tp = 4; tp < T_; ++tp) {
            // ring 8: writing slot tp&7 kills e(tp-8); consumer read it during
            // step tp-9 => safe when ccnt >= tp-8.
            if (tp > ccached + 8) {
                ccached = s_ccnt;
                while (tp > ccached + 8) { __nanosleep(200); ccached = s_ccnt; }
            }
            const int j = tp & 3;
            const float4 nz = rnz[j];
            const float4 x0 = rx0[j];
            const float4 x1 = rx1[j];
            int tl = tp + 4; if (tl > T_ - 1) tl = T_ - 1;
            rnz[j] = *(const float4*)(nz_base + (size_t)tl * H_);
            rx0[j] = __ldg((const float4*)(in_base + tl * I_));
            rx1[j] = __ldg((const float4*)(in_base + tl * I_ + 4));

            const float nza[4] = {nz.x, nz.y, nz.z, nz.w};
            float e[4];
            #pragma unroll
            for (int u = 0; u < 4; ++u) {
                float pp = fmaf(NOISE_STD_, nza[u], negmc[u]);
                pp = fmaf(x0.x, wif[0][u], pp);
                pp = fmaf(x0.y, wif[1][u], pp);
                pp = fmaf(x0.z, wif[2][u], pp);
                pp = fmaf(x0.w, wif[3][u], pp);
                pp = fmaf(x1.x, wif[4][u], pp);
                pp = fmaf(x1.y, wif[5][u], pp);
                pp = fmaf(x1.z, wif[6][u], pp);
                pp = fmaf(x1.w, wif[7][u], pp);
                e[u] = pp;
            }
            *(float4*)&s_e[tp & (RING_ - 1)][k0] = make_float4(e[0], e[1], e[2], e[3]);

            if ((tp & 3) == 3) {
                __threadfence_block();
                if (lane == 0) s_pcnt[pw] = tp + 1;
            }
        }
    } else if (w == 2) {
        // =================== EPILOGUE (warp 2, alone on SMSP2) ===================
        const float so0 = (so[0] / (float)H_) * SO_;
        const float so1 = (so[1] / (float)H_) * SO_;
        float wo0f[16], wo1f[16];
        #pragma unroll
        for (int jb = 0; jb < 4; ++jb) {
            const int k0 = jb * 128 + lane * 4;
            const float4 wA = *(const float4*)(wo + k0 * 2);
            const float4 wB = *(const float4*)(wo + k0 * 2 + 4);
            const int q = jb * 4;
            wo0f[q+0]=wA.x*so0; wo1f[q+0]=wA.y*so1; wo0f[q+1]=wA.z*so0; wo1f[q+1]=wA.w*so1;
            wo0f[q+2]=wB.x*so0; wo1f[q+2]=wB.y*so1; wo0f[q+3]=wB.z*so0; wo1f[q+3]=wB.w*so1;
        }
        float* traj_base = traj + (size_t)b * T_ * H_ + lane * 4;
        float* out_base  = out  + (size_t)b * T_ * O_;
        __syncthreads();

        int ccached = 0;
        #pragma unroll 2
        for (int te = 0; te < T_; ++te) {
            if (ccached < te + 1) {
                ccached = s_ccnt;
                while (ccached < te + 1) { __nanosleep(150); ccached = s_ccnt; }
            }
            const int slot = te & (RING_ - 1);
            float4 h4[4];
            #pragma unroll
            for (int jb = 0; jb < 4; ++jb)
                h4[jb] = ldsv4(&s_h[slot][jb * 128 + lane * 4]);

            float o0A = 0.f, o0B = 0.f, o1A = 0.f, o1B = 0.f;
            const float hv[16] = {h4[0].x,h4[0].y,h4[0].z,h4[0].w,
                                  h4[1].x,h4[1].y,h4[1].z,h4[1].w,
                                  h4[2].x,h4[2].y,h4[2].z,h4[2].w,
                                  h4[3].x,h4[3].y,h4[3].z,h4[3].w};
            #pragma unroll
            for (int q = 0; q < 8; ++q) {
                const float rA = tanh_mufu(hv[q]);
                const float rB = tanh_mufu(hv[q + 8]);
                o0A = fmaf(rA, wo0f[q], o0A);   o0B = fmaf(rB, wo0f[q+8], o0B);
                o1A = fmaf(rA, wo1f[q], o1A);   o1B = fmaf(rB, wo1f[q+8], o1B);
            }
            const int U0 = redux_add_s32(__float2int_rn(o0A + o0B));
            const int U1 = redux_add_s32(__float2int_rn(o1A + o1B));

            #pragma unroll
            for (int jb = 0; jb < 4; ++jb)
                *(float4*)(traj_base + (size_t)te * H_ + jb * 128) = h4[jb];

            if (lane == 0) {
                const float o0 = (float)U0 * (1.0f / SO_);
                const float o1 = (float)U1 * (1.0f / SO_);
                *(float2*)(out_base + (size_t)te * O_) = make_float2(o0, o1);
                s_ecnt = te + 1;               // publish every step (gates h-ring reuse)
            }
        }
    } else {
        // =================== CONSUMER (warp 3, alone on SMSP3) ===================
        float m0f[16], m1f[16], n0f[16], n1f[16], h[16];
        #pragma unroll
        for (int jb = 0; jb < 4; ++jb) {
            const int k0 = jb * 128 + lane * 4;
            const float4 mA = *(const float4*)(m + k0 * 2);
            const float4 mB = *(const float4*)(m + k0 * 2 + 4);
            const float4 nA = *(const float4*)(n + k0 * 2);
            const float4 nB = *(const float4*)(n + k0 * 2 + 4);
            const float4 hh = *(const float4*)(h0 + k0);
            const int q = jb * 4;
            m0f[q+0]=mA.x*cm;  m1f[q+0]=mA.y*cm;  m0f[q+1]=mA.z*cm;  m1f[q+1]=mA.w*cm;
            m0f[q+2]=mB.x*cm;  m1f[q+2]=mB.y*cm;  m0f[q+3]=mB.z*cm;  m1f[q+3]=mB.w*cm;
            n0f[q+0]=nA.x*SA_; n1f[q+0]=nA.y*SA_; n0f[q+1]=nA.z*SA_; n1f[q+1]=nA.w*SA_;
            n0f[q+2]=nB.x*SA_; n1f[q+2]=nB.y*SA_; n0f[q+3]=nB.z*SA_; n1f[q+3]=nB.w*SA_;
            h[q+0]=hh.x; h[q+1]=hh.y; h[q+2]=hh.z; h[q+3]=hh.w;
        }

        // a(0): single-warp magic REDUX
        float A0b, A1b;
        {
            float pa0 = 0.0f, pa1 = 0.0f;
            #pragma unroll
            for (int q = 0; q < 16; ++q) {
                const float r = tanh_mufu(h[q]);
                pa0 = fmaf(r, n0f[q], pa0);
                pa1 = fmaf(r, n1f[q], pa1);
            }
            A0b = __int_as_float(redux_add_s32(__float_as_int(pa0 + MAGIC_F)) + REBIAS_I);
            A1b = __int_as_float(redux_add_s32(__float_as_int(pa1 + MAGIC_F)) + REBIAS_I);
        }
        __syncthreads();

        // hb(0) = 0.8*h0 + e(0)   (e carries noise+proj+negmc)
        float hb[16];
        #pragma unroll
        for (int jb = 0; jb < 4; ++jb) {
            const float4 e4 = ldsv4(&s_e[0][jb * 128 + lane * 4]);
            const int q = jb * 4;
            hb[q+0] = fmaf(1.0f - ALPHA_, h[q+0], e4.x);
            hb[q+1] = fmaf(1.0f - ALPHA_, h[q+1], e4.y);
            hb[q+2] = fmaf(1.0f - ALPHA_, h[q+2], e4.z);
            hb[q+3] = fmaf(1.0f - ALPHA_, h[q+3], e4.w);
        }
        int avail = 4, ecached = 0;

        #pragma unroll 2
        for (int t = 0; t < T_; ++t) {
            // h(t+1) = hb + A0*m0 + A1*m1  (bias cancels via negmc inside hb)
            #pragma unroll
            for (int q = 0; q < 16; ++q) {
                float hx = fmaf(A0b, m0f[q], hb[q]);
                hx       = fmaf(A1b, m1f[q], hx);
                h[q] = hx;
            }
            // hand h to epilogue (smem, cheap) — replaces 4x STG.128
            {
                const int slot = t & (RING_ - 1);
                #pragma unroll
                for (int jb = 0; jb < 4; ++jb)
                    *(float4*)&s_h[slot][jb * 128 + lane * 4] =
                        make_float4(h[jb*4+0], h[jb*4+1], h[jb*4+2], h[jb*4+3]);
            }
            // tanh + a-dots only (o-dots offloaded)
            float a0A = 0.f, a0B = 0.f, a1A = 0.f, a1B = 0.f;
            #pragma unroll
            for (int q = 0; q < 8; ++q) {
                const float rA = tanh_mufu(h[q]);
                const float rB = tanh_mufu(h[q + 8]);
                a0A = fmaf(rA, n0f[q], a0A);    a0B = fmaf(rB, n0f[q+8], a0B);
                a1A = fmaf(rA, n1f[q], a1A);    a1B = fmaf(rB, n1f[q+8], a1B);
            }
            const int W0 = redux_add_s32(__float_as_int((a0A + a0B) + MAGIC_F));
            const int W1 = redux_add_s32(__float_as_int((a1A + a1B) + MAGIC_F));

            // e(t+1) + hb(t+1) while REDUX is in flight
            int tn = t + 1; if (tn > T_ - 1) tn = T_ - 1;
            if (avail < tn + 1) {
                do {
                    avail = min(min(s_pcnt[0], s_pcnt[1]), min(s_pcnt[2], s_pcnt[3]));
                } while (avail < tn + 1);
            }
            {
                const int slot = tn & (RING_ - 1);
                #pragma unroll
                for (int jb = 0; jb < 4; ++jb) {
                    const float4 e4 = ldsv4(&s_e[slot][jb * 128 + lane * 4]);
                    const int q = jb * 4;
                    hb[q+0] = fmaf(1.0f - ALPHA_, h[q+0], e4.x);   // FFMA-imm, rt=1
                    hb[q+1] = fmaf(1.0f - ALPHA_, h[q+1], e4.y);
                    hb[q+2] = fmaf(1.0f - ALPHA_, h[q+2], e4.z);
                    hb[q+3] = fmaf(1.0f - ALPHA_, h[q+3], e4.w);
                }
            }
            A0b = __int_as_float(W0 + REBIAS_I);
            A1b = __int_as_float(W1 + REBIAS_I);

            if ((t & 3) == 3) {                // publish progress (gates prod + epi)
                __syncwarp();
                __threadfence_block();
                if (lane == 0) s_ccnt = t + 1;
            }
            // h-ring reuse: writing slot (t+1)&7 kills h(t-7); need ecnt >= t-6.
            if (t + 1 < T_ && (t + 1) > ecached + 7) {
                ecached = s_ecnt;
                while ((t + 1) > ecached + 7) { __nanosleep(100); ecached = s_ecnt; }
            }
        }
    }
}

extern "C" void kernel_launch(void* const* d_in, const int* in_sizes, int n_in,
                              void* d_out, int out_size) {
    const float* input = (const float*)d_in[0];
    const float* noise = (const float*)d_in[1];
    const float* wi    = (const float*)d_in[2];
    const float* si    = (const float*)d_in[3];
    const float* m     = (const float*)d_in[4];
    const float* n     = (const float*)d_in[5];
    const float* wo    = (const float*)d_in[6];
    const float* so    = (const float*)d_in[7];
    const float* h0    = (const float*)d_in[8];

    float* out  = (float*)d_out;                         // (B,T,O) first
    float* traj = (float*)d_out + (size_t)B_ * T_ * O_;  // then (B,T,H)

    lowrank_rnn_kernel<<<B_, NT_>>>(input, noise, wi, si, m, n, wo, so, h0,
                                    out, traj);
}

// round 15
// speedup vs baseline: 1.6869x; 1.6869x over previous
#include <cuda_runtime.h>
#include <cuda_bf16.h>

#define B_ 64
#define T_ 1024
#define I_ 8
#define H_ 512
#define O_ 2
#define NOISE_STD_ 0.05f
#define ALPHA_ 0.2f

#define NT_    192          // w3=consumer(SMSP3), w2=epilogue(SMSP2), w0/w1/w4/w5=producers
#define RING_  16           // e-ring slots (32 KB)

#define SA_      8192.0f    // 2^13 scale for recurrence dots
#define SO_      2097152.0f // 2^21 scale for output dots
#define MAGIC_F  12582912.0f        // 2^23 + 2^22 round-to-int bias
// Single-warp REDUX of 32 biased floats: bias = 32*0x4B400000 mod 2^32 = 0x68000000.
// Re-bias: + (0x4B400000 - 0x68000000) = 0xE3400000.
#define REBIAS_I ((int)0xE3400000u)

__device__ __forceinline__ float tanh_mufu(float x) {
    float r; asm("tanh.approx.f32 %0, %1;" : "=f"(r) : "f"(x)); return r;
}
__device__ __forceinline__ int redux_add_s32(int v) {
    int r; asm volatile("redux.sync.add.s32 %0, %1, 0xffffffff;" : "=r"(r) : "r"(v)); return r;
}
__device__ __forceinline__ float4 ldsv4(const float* p) {
    float4 v;
    unsigned a = (unsigned)__cvta_generic_to_shared(p);
    asm volatile("ld.volatile.shared.v4.f32 {%0,%1,%2,%3}, [%4];"
                 : "=f"(v.x), "=f"(v.y), "=f"(v.z), "=f"(v.w) : "r"(a));
    return v;
}
// L2-only 128-bit global load (bypass L1: consumer's STG must be observed)
__device__ __forceinline__ float4 ldgcg4(const float* p) {
    float4 v;
    asm volatile("ld.global.cg.v4.f32 {%0,%1,%2,%3}, [%4];"
                 : "=f"(v.x), "=f"(v.y), "=f"(v.z), "=f"(v.w) : "l"(p));
    return v;
}

__global__ __launch_bounds__(NT_, 1)
void lowrank_rnn_kernel(const float* __restrict__ input,   // (B,T,I)
                        const float* __restrict__ noise,   // (B,T,H)
                        const float* __restrict__ wi,      // (I,H)
                        const float* __restrict__ si,      // (I,)
                        const float* __restrict__ m,       // (H,R)
                        const float* __restrict__ n,       // (H,R)
                        const float* __restrict__ wo,      // (H,O)
                        const float* __restrict__ so,      // (O,)
                        const float* __restrict__ h0,      // (H,)
                        float* __restrict__ out,           // (B,T,O)
                        float* __restrict__ traj)          // (B,T,H)
{
    __shared__ float s_e[RING_][H_];       // e(t) = 0.05nz + alpha*proj + negmc
    __shared__ volatile int s_pcnt[4];     // producers: e ready through step pcnt-1
    __shared__ volatile int s_ccnt;        // consumer: steps finished (traj visible)

    const int b    = blockIdx.x;
    const int tid  = threadIdx.x;
    const int w    = tid >> 5;
    const int lane = tid & 31;

    const float cm = (ALPHA_ / (float)H_) / SA_;   // alpha/H and 1/Sa folded into m

    if (w != 3 && w != 2) {
        // =================== PRODUCER (warps 0,1,4,5) ===================
        const int pw = (w < 2) ? w : w - 2;        // 0..3
        const int k0 = (pw * 32 + lane) * 4;

        float wif[I_][4];                          // wi * si * alpha
        #pragma unroll
        for (int i = 0; i < I_; ++i) {
            const float4 ww = *(const float4*)(wi + i * H_ + k0);
            const float  s  = si[i] * ALPHA_;
            wif[i][0] = ww.x * s; wif[i][1] = ww.y * s;
            wif[i][2] = ww.z * s; wif[i][3] = ww.w * s;
        }
        float negmc[4];                            // -MAGIC*(m0f+m1f), folded into e
        {
            const float4 mA = *(const float4*)(m + k0 * 2);
            const float4 mB = *(const float4*)(m + k0 * 2 + 4);
            negmc[0] = -MAGIC_F * (mA.x * cm + mA.y * cm);
            negmc[1] = -MAGIC_F * (mA.z * cm + mA.w * cm);
            negmc[2] = -MAGIC_F * (mB.x * cm + mB.y * cm);
            negmc[3] = -MAGIC_F * (mB.z * cm + mB.w * cm);
        }
        const float* nz_base = noise + (size_t)b * T_ * H_ + k0;
        const float* in_base = input + (size_t)b * T_ * I_;

        if (tid == 0) s_ccnt = 0;
        // prologue: produce steps 0..7
        for (int s = 0; s < 8; ++s) {
            const float4 nz = *(const float4*)(nz_base + (size_t)s * H_);
            const float4 x0 = __ldg((const float4*)(in_base + s * I_));
            const float4 x1 = __ldg((const float4*)(in_base + s * I_ + 4));
            const float nza[4] = {nz.x, nz.y, nz.z, nz.w};
            float e[4];
            #pragma unroll
            for (int u = 0; u < 4; ++u) {
                float pp = fmaf(NOISE_STD_, nza[u], negmc[u]);
                pp = fmaf(x0.x, wif[0][u], pp);
                pp = fmaf(x0.y, wif[1][u], pp);
                pp = fmaf(x0.z, wif[2][u], pp);
                pp = fmaf(x0.w, wif[3][u], pp);
                pp = fmaf(x1.x, wif[4][u], pp);
                pp = fmaf(x1.y, wif[5][u], pp);
                pp = fmaf(x1.z, wif[6][u], pp);
                pp = fmaf(x1.w, wif[7][u], pp);
                e[u] = pp;
            }
            *(float4*)&s_e[s][k0] = make_float4(e[0], e[1], e[2], e[3]);
        }
        if (lane == 0) s_pcnt[pw] = 8;
        // preload LDG ring for steps 8..11
        float4 rnz[4], rx0[4], rx1[4];
        #pragma unroll
        for (int j = 0; j < 4; ++j) {
            const int t = 8 + j;
            rnz[j] = *(const float4*)(nz_base + (size_t)t * H_);
            rx0[j] = __ldg((const float4*)(in_base + t * I_));
            rx1[j] = __ldg((const float4*)(in_base + t * I_ + 4));
        }
        __syncthreads();

        int ccached = 0;
        #pragma unroll 4
        for (int tp = 8; tp < T_; ++tp) {
            if (tp > ccached + 12) {               // ring 16, consumer lag guard
                ccached = s_ccnt;
                while (tp > ccached + 12) { __nanosleep(200); ccached = s_ccnt; }
            }
            const int j = tp & 3;
            const float4 nz = rnz[j];
            const float4 x0 = rx0[j];
            const float4 x1 = rx1[j];
            int tl = tp + 4; if (tl > T_ - 1) tl = T_ - 1;
            rnz[j] = *(const float4*)(nz_base + (size_t)tl * H_);
            rx0[j] = __ldg((const float4*)(in_base + tl * I_));
            rx1[j] = __ldg((const float4*)(in_base + tl * I_ + 4));

            const float nza[4] = {nz.x, nz.y, nz.z, nz.w};
            float e[4];
            #pragma unroll
            for (int u = 0; u < 4; ++u) {
                float pp = fmaf(NOISE_STD_, nza[u], negmc[u]);
                pp = fmaf(x0.x, wif[0][u], pp);
                pp = fmaf(x0.y, wif[1][u], pp);
                pp = fmaf(x0.z, wif[2][u], pp);
                pp = fmaf(x0.w, wif[3][u], pp);
                pp = fmaf(x1.x, wif[4][u], pp);
                pp = fmaf(x1.y, wif[5][u], pp);
                pp = fmaf(x1.z, wif[6][u], pp);
                pp = fmaf(x1.w, wif[7][u], pp);
                e[u] = pp;
            }
            *(float4*)&s_e[tp & (RING_ - 1)][k0] = make_float4(e[0], e[1], e[2], e[3]);

            if ((tp & 3) == 3) {
                __threadfence_block();
                if (lane == 0) s_pcnt[pw] = tp + 1;
            }
        }
    } else if (w == 2) {
        // ======== EPILOGUE (warp 2, SMSP2): out[] from traj, purely downstream ========
        const float so0 = (so[0] / (float)H_) * SO_;
        const float so1 = (so[1] / (float)H_) * SO_;
        float wo0f[16], wo1f[16];
        #pragma unroll
        for (int jb = 0; jb < 4; ++jb) {
            const int k0 = jb * 128 + lane * 4;
            const float4 wA = *(const float4*)(wo + k0 * 2);
            const float4 wB = *(const float4*)(wo + k0 * 2 + 4);
            const int q = jb * 4;
            wo0f[q+0]=wA.x*so0; wo1f[q+0]=wA.y*so1; wo0f[q+1]=wA.z*so0; wo1f[q+1]=wA.w*so1;
            wo0f[q+2]=wB.x*so0; wo1f[q+2]=wB.y*so1; wo0f[q+3]=wB.z*so0; wo1f[q+3]=wB.w*so1;
        }
        const float* traj_base = traj + (size_t)b * T_ * H_ + lane * 4;
        float*       out_base  = out  + (size_t)b * T_ * O_;
        __syncthreads();

        int ccached = 0;
        for (int tc = 0; tc < T_; tc += 4) {       // chunks of 4 steps
            if (ccached < tc + 4) {
                ccached = s_ccnt;
                while (ccached < tc + 4) { __nanosleep(200); ccached = s_ccnt; }
            }
            // 16 independent LDG.128 in flight (L2 latency amortized over chunk)
            float4 h4[4][4];
            #pragma unroll
            for (int s = 0; s < 4; ++s)
                #pragma unroll
                for (int jb = 0; jb < 4; ++jb)
                    h4[s][jb] = ldgcg4(traj_base + (size_t)(tc + s) * H_ + jb * 128);

            #pragma unroll
            for (int s = 0; s < 4; ++s) {
                const float hv[16] = {h4[s][0].x,h4[s][0].y,h4[s][0].z,h4[s][0].w,
                                      h4[s][1].x,h4[s][1].y,h4[s][1].z,h4[s][1].w,
                                      h4[s][2].x,h4[s][2].y,h4[s][2].z,h4[s][2].w,
                                      h4[s][3].x,h4[s][3].y,h4[s][3].z,h4[s][3].w};
                float o0A = 0.f, o0B = 0.f, o1A = 0.f, o1B = 0.f;
                #pragma unroll
                for (int q = 0; q < 8; ++q) {
                    const float rA = tanh_mufu(hv[q]);
                    const float rB = tanh_mufu(hv[q + 8]);
                    o0A = fmaf(rA, wo0f[q], o0A);   o0B = fmaf(rB, wo0f[q+8], o0B);
                    o1A = fmaf(rA, wo1f[q], o1A);   o1B = fmaf(rB, wo1f[q+8], o1B);
                }
                const int U0 = redux_add_s32(__float2int_rn(o0A + o0B));
                const int U1 = redux_add_s32(__float2int_rn(o1A + o1B));
                if (lane == 0) {
                    const float o0 = (float)U0 * (1.0f / SO_);
                    const float o1 = (float)U1 * (1.0f / SO_);
                    *(float2*)(out_base + (size_t)(tc + s) * O_) = make_float2(o0, o1);
                }
            }
        }
    } else {
        // =================== CONSUMER (warp 3, alone on SMSP3) ===================
        float m0f[16], m1f[16], n0f[16], n1f[16], h[16];
        #pragma unroll
        for (int jb = 0; jb < 4; ++jb) {
            const int k0 = jb * 128 + lane * 4;
            const float4 mA = *(const float4*)(m + k0 * 2);
            const float4 mB = *(const float4*)(m + k0 * 2 + 4);
            const float4 nA = *(const float4*)(n + k0 * 2);
            const float4 nB = *(const float4*)(n + k0 * 2 + 4);
            const float4 hh = *(const float4*)(h0 + k0);
            const int q = jb * 4;
            m0f[q+0]=mA.x*cm;  m1f[q+0]=mA.y*cm;  m0f[q+1]=mA.z*cm;  m1f[q+1]=mA.w*cm;
            m0f[q+2]=mB.x*cm;  m1f[q+2]=mB.y*cm;  m0f[q+3]=mB.z*cm;  m1f[q+3]=mB.w*cm;
            n0f[q+0]=nA.x*SA_; n1f[q+0]=nA.y*SA_; n0f[q+1]=nA.z*SA_; n1f[q+1]=nA.w*SA_;
            n0f[q+2]=nB.x*SA_; n1f[q+2]=nB.y*SA_; n0f[q+3]=nB.z*SA_; n1f[q+3]=nB.w*SA_;
            h[q+0]=hh.x; h[q+1]=hh.y; h[q+2]=hh.z; h[q+3]=hh.w;
        }
        float* traj_base = traj + (size_t)b * T_ * H_ + lane * 4;

        // a(0): single-warp magic REDUX
        float A0b, A1b;
        {
            float pa0 = 0.0f, pa1 = 0.0f;
            #pragma unroll
            for (int q = 0; q < 16; ++q) {
                const float r = tanh_mufu(h[q]);
                pa0 = fmaf(r, n0f[q], pa0);
                pa1 = fmaf(r, n1f[q], pa1);
            }
            A0b = __int_as_float(redux_add_s32(__float_as_int(pa0 + MAGIC_F)) + REBIAS_I);
            A1b = __int_as_float(redux_add_s32(__float_as_int(pa1 + MAGIC_F)) + REBIAS_I);
        }
        __syncthreads();

        float4 e4[4];
        #pragma unroll
        for (int jb = 0; jb < 4; ++jb)
            e4[jb] = ldsv4(&s_e[0][jb * 128 + lane * 4]);
        int avail = 8;

        #pragma unroll 2
        for (int t = 0; t < T_; ++t) {
            const float ea[16] = {e4[0].x,e4[0].y,e4[0].z,e4[0].w,
                                  e4[1].x,e4[1].y,e4[1].z,e4[1].w,
                                  e4[2].x,e4[2].y,e4[2].z,e4[2].w,
                                  e4[3].x,e4[3].y,e4[3].z,e4[3].w};
            #pragma unroll
            for (int q = 0; q < 16; ++q) {
                const float hb = fmaf(1.0f - ALPHA_, h[q], ea[q]);   // FFMA-imm
                float hx = fmaf(A0b, m0f[q], hb);
                hx       = fmaf(A1b, m1f[q], hx);
                h[q] = hx;
            }
            // traj[t] = h_{t+1}, 4x STG.128 coalesced
            #pragma unroll
            for (int jb = 0; jb < 4; ++jb)
                *(float4*)(traj_base + (size_t)t * H_ + jb * 128) =
                    make_float4(h[jb*4+0], h[jb*4+1], h[jb*4+2], h[jb*4+3]);

            // tanh + a-dots ONLY (o-dots offloaded to epilogue warp)
            float a0A = 0.f, a0B = 0.f, a1A = 0.f, a1B = 0.f;
            #pragma unroll
            for (int q = 0; q < 8; ++q) {
                const float rA = tanh_mufu(h[q]);
                const float rB = tanh_mufu(h[q + 8]);
                a0A = fmaf(rA, n0f[q], a0A);    a0B = fmaf(rB, n0f[q+8], a0B);
                a1A = fmaf(rA, n1f[q], a1A);    a1B = fmaf(rB, n1f[q+8], a1B);
            }
            const int W0 = redux_add_s32(__float_as_int((a0A + a0B) + MAGIC_F));
            const int W1 = redux_add_s32(__float_as_int((a1A + a1B) + MAGIC_F));

            // e(t+1) prefetch while REDUX is in flight
            int tn = t + 1; if (tn > T_ - 1) tn = T_ - 1;
            if (avail < tn + 1) {
                do {
                    avail = min(min(s_pcnt[0], s_pcnt[1]), min(s_pcnt[2], s_pcnt[3]));
                } while (avail < tn + 1);
            }
            {
                const int slot = tn & (RING_ - 1);
                #pragma unroll
                for (int jb = 0; jb < 4; ++jb)
                    e4[jb] = ldsv4(&s_e[slot][jb * 128 + lane * 4]);
            }
            A0b = __int_as_float(W0 + REBIAS_I);
            A1b = __int_as_float(W1 + REBIAS_I);

            if ((t & 3) == 3) {                // orders traj STGs, then publish
                __syncwarp();
                __threadfence_block();
                if (lane == 0) s_ccnt = t + 1;
            }
        }
    }
}

extern "C" void kernel_launch(void* const* d_in, const int* in_sizes, int n_in,
                              void* d_out, int out_size) {
    const float* input = (const float*)d_in[0];
    const float* noise = (const float*)d_in[1];
    const float* wi    = (const float*)d_in[2];
    const float* si    = (const float*)d_in[3];
    const float* m     = (const float*)d_in[4];
    const float* n     = (const float*)d_in[5];
    const float* wo    = (const float*)d_in[6];
    const float* so    = (const float*)d_in[7];
    const float* h0    = (const float*)d_in[8];

    float* out  = (float*)d_out;                         // (B,T,O) first
    float* traj = (float*)d_out + (size_t)B_ * T_ * O_;  // then (B,T,H)

    lowrank_rnn_kernel<<<B_, NT_>>>(input, noise, wi, si, m, n, wo, so, h0,
                                    out, traj);
}